// round 4
// baseline (speedup 1.0000x reference)
#include <cuda_runtime.h>

#define TT 336

// ---------------- device scratch ----------------
__device__ float dW1g[2 * 80 * 280];        // [dir][k][up(35)][gate(4)][2], i/f/o prescaled 0.5
__device__ float dB1g[2 * 280];             // [dir][up][gate][2]
__device__ float dW2g[2 * 161 * 88];        // [dir][k][up(11)][gate(4)][2]
__device__ float dB2g[2 * 88];
__device__ float dH1T[64 * 336 * 140 * 32]; // [bblk][t][k(140)][r(32)]
__device__ float dH2[2048 * 336 * 42];      // [b][t][42]

// ---------------- f32x2 helpers ----------------
__device__ __forceinline__ float2 up2(unsigned long long v) {
    float2 r;
    asm("mov.b64 {%0, %1}, %2;" : "=f"(r.x), "=f"(r.y) : "l"(v));
    return r;
}
__device__ __forceinline__ void fma2(unsigned long long& d, unsigned long long a, unsigned long long b) {
    asm("fma.rn.f32x2 %0, %1, %2, %3;" : "=l"(d) : "l"(a), "l"(b), "l"(d));
}
__device__ __forceinline__ float tanha(float x) {
    float y;
    asm("tanh.approx.f32 %0, %1;" : "=f"(y) : "f"(x));
    return y;
}
// i/f/o pre-acts are prescaled by 0.5 -> sigmoid(z) = 0.5 + 0.5*tanh(z/2)
__device__ __forceinline__ void lstm_act(float2 yi, float2 yf, float2 yg, float2 yo,
                                         float2& c, float2& h) {
    float six = 0.5f + 0.5f * tanha(yi.x), siy = 0.5f + 0.5f * tanha(yi.y);
    float sfx = 0.5f + 0.5f * tanha(yf.x), sfy = 0.5f + 0.5f * tanha(yf.y);
    float tgx = tanha(yg.x), tgy = tanha(yg.y);
    float sox = 0.5f + 0.5f * tanha(yo.x), soy = 0.5f + 0.5f * tanha(yo.y);
    c.x = sfx * c.x + six * tgx;
    c.y = sfy * c.y + siy * tgy;
    h.x = sox * tanha(c.x);
    h.y = soy * tanha(c.y);
}
__device__ __forceinline__ float2 sum3(unsigned long long a, unsigned long long b, float2 bias) {
    float2 fa = up2(a), fb = up2(b);
    return make_float2(fa.x + fb.x + bias.x, fa.y + fb.y + bias.y);
}

// ---------------- weight prep ----------------
__global__ void prep1(const float* wfih, const float* wfhh, const float* bfih, const float* bfhh,
                      const float* wbih, const float* wbhh, const float* bbih, const float* bbhh) {
    int idx = blockIdx.x * blockDim.x + threadIdx.x;
    if (idx < 2 * 80 * 280) {
        int d = idx / 22400, rem = idx % 22400;
        int k = rem / 280, j = rem % 280;
        int up = j / 8, g = (j / 2) % 4, e = j & 1;
        int u = up * 2 + e, row = g * 70 + u;
        const float* wih = d ? wbih : wfih;
        const float* whh = d ? wbhh : wfhh;
        float v = (k < 10) ? wih[row * 10 + k] : whh[row * 70 + (k - 10)];
        if (g != 2) v *= 0.5f;
        dW1g[idx] = v;
    }
    if (idx < 2 * 280) {
        int d = idx / 280, j = idx % 280;
        int up = j / 8, g = (j / 2) % 4, e = j & 1;
        int u = up * 2 + e, row = g * 70 + u;
        const float* bih = d ? bbih : bfih;
        const float* bhh = d ? bbhh : bfhh;
        float v = bih[row] + bhh[row];
        if (g != 2) v *= 0.5f;
        dB1g[idx] = v;
    }
}

__global__ void prep2(const float* wfih, const float* wfhh, const float* bfih, const float* bfhh,
                      const float* wbih, const float* wbhh, const float* bbih, const float* bbhh) {
    int idx = blockIdx.x * blockDim.x + threadIdx.x;
    if (idx < 2 * 161 * 88) {
        int d = idx / (161 * 88), rem = idx % (161 * 88);
        int k = rem / 88, j = rem % 88;
        int up = j / 8, g = (j / 2) % 4, e = j & 1;
        int u = up * 2 + e;
        float v = 0.f;
        if (u < 21) {
            int row = g * 21 + u;
            const float* wih = d ? wbih : wfih;
            const float* whh = d ? wbhh : wfhh;
            v = (k < 140) ? wih[row * 140 + k] : whh[row * 21 + (k - 140)];
            if (g != 2) v *= 0.5f;
        }
        dW2g[idx] = v;
    }
    if (idx < 2 * 88) {
        int d = idx / 88, j = idx % 88;
        int up = j / 8, g = (j / 2) % 4, e = j & 1;
        int u = up * 2 + e;
        float v = 0.f;
        if (u < 21) {
            int row = g * 21 + u;
            const float* bih = d ? bbih : bfih;
            const float* bhh = d ? bbhh : bfhh;
            v = bih[row] + bhh[row];
            if (g != 2) v *= 0.5f;
        }
        dB2g[idx] = v;
    }
}

// ---------------- layer 1: F=10 -> H=70, bidirectional ----------------
// grid (64, 2), 560 threads. 2-way k-split: group = tid/280 does k in [g*40, g*40+40).
// Within a group: up = q%35 (2 units), rg = q/35 (4 rows). Each thread finally owns
// 2 rows (r0+2*grp .. +1) x 2 units; partials for the other 2 rows exchanged via sRed.
__global__ __launch_bounds__(560, 1) void lstm1(const float* __restrict__ x) {
    extern __shared__ float sm[];
    float* sW = sm;                 // 80*280
    float* sB = sW + 80 * 280;      // 280
    float* sIn = sB + 280;          // 80*68  (value duplicated pairs: [k][2r..2r+1] = {v,v})
    float* sRed = sIn + 80 * 68;    // 560*18
    const int dir = blockIdx.y, bblk = blockIdx.x;
    const int b0 = bblk * 32;
    const int tid = threadIdx.x;

    const float* gW = dW1g + dir * 22400;
    for (int i = tid; i < 22400; i += 560) sW[i] = gW[i];
    for (int i = tid; i < 280; i += 560) sB[i] = dB1g[dir * 280 + i];
    for (int i = tid; i < 80 * 68; i += 560) sIn[i] = 0.f;

    const int grp = tid / 280, q = tid % 280;
    const int up = q % 35, rg = q / 35;
    const int u0 = up * 2, r0 = rg * 4;
    const int rown = r0 + grp * 2;          // owned rows: rown, rown+1
    float2 c0 = make_float2(0.f, 0.f), c1 = make_float2(0.f, 0.f);
    __syncthreads();

    const float2 bia = *(const float2*)&sB[up * 8 + 0];
    const float2 bfa = *(const float2*)&sB[up * 8 + 2];
    const float2 bga = *(const float2*)&sB[up * 8 + 4];
    const float2 boa = *(const float2*)&sB[up * 8 + 6];

    const float* pa = sIn + grp * 40 * 68 + 2 * r0;
    const float* pw = sW + grp * 40 * 280 + up * 8;
    float* myRed = sRed + tid * 18;
    const float* peRed = sRed + (grp ? tid - 280 : tid + 280) * 18;
    const int jn = 2 * (1 - grp);           // non-owned row-offset in acc
    const int jo = 2 * grp;                 // owned row-offset in acc

    // x prefetch (one element per thread, tid<320)
    const int xrow = tid / 10, xf = tid % 10;
    float xr = 0.f;
    if (tid < 320) xr = x[((b0 + xrow) * TT + (dir ? TT - 1 : 0)) * 10 + xf];

    for (int s = 0; s < TT; s++) {
        const int t = dir ? TT - 1 - s : s;
        if (tid < 320) {
            float2 d2 = make_float2(xr, xr);
            *(float2*)&sIn[xf * 68 + 2 * xrow] = d2;
        }
        __syncthreads();
        if (s + 1 < TT && tid < 320) {
            int tn = dir ? TT - 2 - s : s + 1;
            xr = x[((b0 + xrow) * TT + tn) * 10 + xf];
        }

        unsigned long long acc[4][4];
#pragma unroll
        for (int j = 0; j < 4; j++)
#pragma unroll
            for (int g = 0; g < 4; g++) acc[j][g] = 0ull;

#pragma unroll
        for (int k = 0; k < 40; k++) {
            ulonglong2 a01 = *(const ulonglong2*)(pa + k * 68);       // {v0,v0},{v1,v1}
            ulonglong2 a23 = *(const ulonglong2*)(pa + k * 68 + 4);   // {v2,v2},{v3,v3}
            ulonglong2 w01 = *(const ulonglong2*)(pw + k * 280);      // gates 0,1 (u0,u0+1)
            ulonglong2 w23 = *(const ulonglong2*)(pw + k * 280 + 4);  // gates 2,3
            fma2(acc[0][0], a01.x, w01.x); fma2(acc[0][1], a01.x, w01.y);
            fma2(acc[0][2], a01.x, w23.x); fma2(acc[0][3], a01.x, w23.y);
            fma2(acc[1][0], a01.y, w01.x); fma2(acc[1][1], a01.y, w01.y);
            fma2(acc[1][2], a01.y, w23.x); fma2(acc[1][3], a01.y, w23.y);
            fma2(acc[2][0], a23.x, w01.x); fma2(acc[2][1], a23.x, w01.y);
            fma2(acc[2][2], a23.x, w23.x); fma2(acc[2][3], a23.x, w23.y);
            fma2(acc[3][0], a23.y, w01.x); fma2(acc[3][1], a23.y, w01.y);
            fma2(acc[3][2], a23.y, w23.x); fma2(acc[3][3], a23.y, w23.y);
        }

        // exchange partials for non-owned rows
#pragma unroll
        for (int jj = 0; jj < 2; jj++)
#pragma unroll
            for (int g = 0; g < 4; g++)
                *(unsigned long long*)&myRed[(jj * 4 + g) * 2] = acc[jn + jj][g];
        __syncthreads();

        float hv[2][2];
#pragma unroll
        for (int jj = 0; jj < 2; jj++) {
            unsigned long long p0 = *(const unsigned long long*)&peRed[(jj * 4 + 0) * 2];
            unsigned long long p1 = *(const unsigned long long*)&peRed[(jj * 4 + 1) * 2];
            unsigned long long p2 = *(const unsigned long long*)&peRed[(jj * 4 + 2) * 2];
            unsigned long long p3 = *(const unsigned long long*)&peRed[(jj * 4 + 3) * 2];
            float2 yi = sum3(acc[jo + jj][0], p0, bia);
            float2 yf = sum3(acc[jo + jj][1], p1, bfa);
            float2 yg = sum3(acc[jo + jj][2], p2, bga);
            float2 yo = sum3(acc[jo + jj][3], p3, boa);
            float2& cc = jj ? c1 : c0;
            float2 h;
            lstm_act(yi, yf, yg, yo, cc, h);
            hv[jj][0] = h.x;
            hv[jj][1] = h.y;
        }

        // h write-back: shared (duplicated) + global blocked-transposed
#pragma unroll
        for (int jj = 0; jj < 2; jj++) {
            int rr = rown + jj;
            *(float2*)&sIn[(10 + u0) * 68 + 2 * rr] = make_float2(hv[jj][0], hv[jj][0]);
            *(float2*)&sIn[(11 + u0) * 68 + 2 * rr] = make_float2(hv[jj][1], hv[jj][1]);
        }
        {
            size_t gb = (size_t)(bblk * TT + t) * 4480 + (dir * 70 + u0) * 32 + rown;
            *(float2*)&dH1T[gb]      = make_float2(hv[0][0], hv[1][0]);
            *(float2*)&dH1T[gb + 32] = make_float2(hv[0][1], hv[1][1]);
        }
        __syncthreads();
    }
}

// ---------------- layer 2: 140 -> H=21 (pad 22), bidirectional ----------------
// grid (64, 2), 352 threads. k-split: group0 k 0..79, group1 k 80..160.
// up = q%11 (2 units incl pad), rg = q/11 (2 rows). Each thread owns row r0+grp.
__global__ __launch_bounds__(352, 1) void lstm2() {
    extern __shared__ float sm[];
    float* sW = sm;                  // 161*88
    float* sB = sW + 161 * 88;       // 88
    float* sIn = sB + 88;            // 161*68 (duplicated pairs)
    float* sRed = sIn + 161 * 68;    // 352*10
    const int dir = blockIdx.y, bblk = blockIdx.x;
    const int b0 = bblk * 32;
    const int tid = threadIdx.x;

    const float* gW = dW2g + dir * 161 * 88;
    for (int i = tid; i < 161 * 88; i += 352) sW[i] = gW[i];
    for (int i = tid; i < 88; i += 352) sB[i] = dB2g[dir * 88 + i];
    for (int i = tid; i < 161 * 68; i += 352) sIn[i] = 0.f;

    const int grp = tid / 176, q = tid % 176;
    const int up = q % 11, rg = q / 11;
    const int u0 = up * 2, r0 = rg * 2;
    const int rown = r0 + grp;
    float2 c = make_float2(0.f, 0.f);
    __syncthreads();

    const float2 bia = *(const float2*)&sB[up * 8 + 0];
    const float2 bfa = *(const float2*)&sB[up * 8 + 2];
    const float2 bga = *(const float2*)&sB[up * 8 + 4];
    const float2 boa = *(const float2*)&sB[up * 8 + 6];

    const int koff = grp * 80, kcnt = grp ? 81 : 80;
    const float* pa = sIn + koff * 68 + 2 * r0;
    const float* pw = sW + koff * 88 + up * 8;
    float* myRed = sRed + tid * 10;
    const float* peRed = sRed + (grp ? tid - 176 : tid + 176) * 10;

    // staging prefetch: 1120 float4 per step, 3-4 per thread
    const int nldg = (tid < 64) ? 4 : 3;
    float4 p[4];
    {
        size_t gb = (size_t)(bblk * TT + (dir ? TT - 1 : 0)) * 4480;
#pragma unroll
        for (int j = 0; j < 4; j++)
            if (j < nldg) p[j] = *(const float4*)&dH1T[gb + (size_t)(tid + j * 352) * 4];
    }

    for (int s = 0; s < TT; s++) {
        const int t = dir ? TT - 1 - s : s;
        // stage input (duplicated) into sIn
#pragma unroll
        for (int j = 0; j < 4; j++) {
            if (j < nldg) {
                int i = tid + j * 352;
                int k = i >> 3, rq = (i & 7) * 4;
                float* dst = &sIn[k * 68 + 2 * rq];
                *(float2*)(dst + 0) = make_float2(p[j].x, p[j].x);
                *(float2*)(dst + 2) = make_float2(p[j].y, p[j].y);
                *(float2*)(dst + 4) = make_float2(p[j].z, p[j].z);
                *(float2*)(dst + 6) = make_float2(p[j].w, p[j].w);
            }
        }
        __syncthreads();
        if (s + 1 < TT) {
            int tn = dir ? TT - 2 - s : s + 1;
            size_t gb = (size_t)(bblk * TT + tn) * 4480;
#pragma unroll
            for (int j = 0; j < 4; j++)
                if (j < nldg) p[j] = *(const float4*)&dH1T[gb + (size_t)(tid + j * 352) * 4];
        }

        unsigned long long acc[2][4];
#pragma unroll
        for (int j = 0; j < 2; j++)
#pragma unroll
            for (int g = 0; g < 4; g++) acc[j][g] = 0ull;

#pragma unroll 9
        for (int k = 0; k < kcnt; k++) {
            ulonglong2 a = *(const ulonglong2*)(pa + k * 68);        // {v0,v0},{v1,v1}
            ulonglong2 w01 = *(const ulonglong2*)(pw + k * 88);
            ulonglong2 w23 = *(const ulonglong2*)(pw + k * 88 + 4);
            fma2(acc[0][0], a.x, w01.x); fma2(acc[0][1], a.x, w01.y);
            fma2(acc[0][2], a.x, w23.x); fma2(acc[0][3], a.x, w23.y);
            fma2(acc[1][0], a.y, w01.x); fma2(acc[1][1], a.y, w01.y);
            fma2(acc[1][2], a.y, w23.x); fma2(acc[1][3], a.y, w23.y);
        }

        // exchange the non-owned row's partials
#pragma unroll
        for (int g = 0; g < 4; g++)
            *(unsigned long long*)&myRed[g * 2] = acc[1 - grp][g];
        __syncthreads();

        unsigned long long p0 = *(const unsigned long long*)&peRed[0];
        unsigned long long p1 = *(const unsigned long long*)&peRed[2];
        unsigned long long p2 = *(const unsigned long long*)&peRed[4];
        unsigned long long p3 = *(const unsigned long long*)&peRed[6];
        float2 yi = sum3(acc[grp][0], p0, bia);
        float2 yf = sum3(acc[grp][1], p1, bfa);
        float2 yg = sum3(acc[grp][2], p2, bga);
        float2 yo = sum3(acc[grp][3], p3, boa);
        float2 h;
        lstm_act(yi, yf, yg, yo, c, h);

        // h write-back (unit u0 always valid; u0+1 valid unless u0==20)
        *(float2*)&sIn[(140 + u0) * 68 + 2 * rown] = make_float2(h.x, h.x);
        size_t ob = (size_t)((b0 + rown) * TT + t) * 42 + dir * 21 + u0;
        dH2[ob] = h.x;
        if (u0 + 1 < 21) {
            *(float2*)&sIn[(141 + u0) * 68 + 2 * rown] = make_float2(h.y, h.y);
            dH2[ob + 1] = h.y;
        }
        __syncthreads();
    }
}

// ---------------- dense head: 42 -> relu 30 -> relu 20 -> 1 ----------------
__global__ __launch_bounds__(256) void dense_head(const float* __restrict__ wd1, const float* __restrict__ bd1,
                                                  const float* __restrict__ wd2, const float* __restrict__ bd2,
                                                  const float* __restrict__ wo, const float* __restrict__ bo,
                                                  float* __restrict__ out) {
    __shared__ float sW1[30 * 42], sb1[30], sW2[20 * 30], sb2[20], swo[20], sbo[1];
    int tid = threadIdx.x;
    for (int i = tid; i < 1260; i += 256) sW1[i] = wd1[i];
    for (int i = tid; i < 600; i += 256) sW2[i] = wd2[i];
    if (tid < 30) sb1[tid] = bd1[tid];
    if (tid < 20) { sb2[tid] = bd2[tid]; swo[tid] = wo[tid]; }
    if (tid == 0) sbo[0] = bo[0];
    __syncthreads();

    int pos = blockIdx.x * 256 + tid;
    float in[42];
    const float* p = dH2 + (size_t)pos * 42;
#pragma unroll
    for (int k = 0; k < 42; k++) in[k] = p[k];

    float a[30];
#pragma unroll
    for (int j = 0; j < 30; j++) {
        float s = sb1[j];
#pragma unroll
        for (int k = 0; k < 42; k++) s += in[k] * sW1[j * 42 + k];
        a[j] = fmaxf(s, 0.f);
    }
    float o = sbo[0];
#pragma unroll
    for (int j = 0; j < 20; j++) {
        float s = sb2[j];
#pragma unroll
        for (int k = 0; k < 30; k++) s += a[k] * sW2[j * 30 + k];
        o += fmaxf(s, 0.f) * swo[j];
    }
    out[pos] = o;
}

// ---------------- launch ----------------
extern "C" void kernel_launch(void* const* d_in, const int* in_sizes, int n_in,
                              void* d_out, int out_size) {
    const float* x = (const float*)d_in[0];

    const int smem1 = (80 * 280 + 280 + 80 * 68 + 560 * 18) * 4;   // 152160 B
    const int smem2 = (161 * 88 + 88 + 161 * 68 + 352 * 10) * 4;   // 113608 B
    cudaFuncSetAttribute(lstm1, cudaFuncAttributeMaxDynamicSharedMemorySize, smem1);
    cudaFuncSetAttribute(lstm2, cudaFuncAttributeMaxDynamicSharedMemorySize, smem2);

    prep1<<<175, 256>>>((const float*)d_in[1], (const float*)d_in[2], (const float*)d_in[3], (const float*)d_in[4],
                        (const float*)d_in[5], (const float*)d_in[6], (const float*)d_in[7], (const float*)d_in[8]);
    prep2<<<111, 256>>>((const float*)d_in[9], (const float*)d_in[10], (const float*)d_in[11], (const float*)d_in[12],
                        (const float*)d_in[13], (const float*)d_in[14], (const float*)d_in[15], (const float*)d_in[16]);

    lstm1<<<dim3(64, 2), 560, smem1>>>(x);
    lstm2<<<dim3(64, 2), 352, smem2>>>();

    dense_head<<<(2048 * 336) / 256, 256>>>((const float*)d_in[17], (const float*)d_in[18],
                                            (const float*)d_in[19], (const float*)d_in[20],
                                            (const float*)d_in[21], (const float*)d_in[22],
                                            (float*)d_out);
}

// round 8
// speedup vs baseline: 1.6498x; 1.6498x over previous
#include <cuda_runtime.h>

#define TT 336

// ---------------- device scratch ----------------
__device__ float dW1g[2 * 80 * 280];        // [dir][k][up(35)][gate(4)][2], i/f/o prescaled 0.5
__device__ float dB1g[2 * 280];             // [dir][up][gate][2]
__device__ float dW2g[2 * 161 * 88];        // [dir][k][up(11)][gate(4)][2]
__device__ float dB2g[2 * 88];
__device__ float dH1T[64 * 336 * 140 * 32]; // [bblk][t][k(140)][r(32)]
__device__ float dH2[2048 * 336 * 42];      // [b][t][42]

typedef unsigned long long ull;

// ---------------- f32x2 helpers ----------------
__device__ __forceinline__ ull pk2(float v) {
    ull r;
    asm("mov.b64 %0, {%1, %1};" : "=l"(r) : "f"(v));
    return r;
}
__device__ __forceinline__ float2 up2(ull v) {
    float2 r;
    asm("mov.b64 {%0, %1}, %2;" : "=f"(r.x), "=f"(r.y) : "l"(v));
    return r;
}
__device__ __forceinline__ void fma2(ull& d, ull a, ull b) {
    asm("fma.rn.f32x2 %0, %1, %2, %3;" : "=l"(d) : "l"(a), "l"(b), "l"(d));
}
__device__ __forceinline__ float tanha(float x) {
    float y;
    asm("tanh.approx.f32 %0, %1;" : "=f"(y) : "f"(x));
    return y;
}
// i/f/o pre-acts prescaled by 0.5 -> sigmoid(z) = 0.5 + 0.5*tanh(z/2)
__device__ __forceinline__ void lstm_act(float2 yi, float2 yf, float2 yg, float2 yo,
                                         float2& c, float2& h) {
    float six = 0.5f + 0.5f * tanha(yi.x), siy = 0.5f + 0.5f * tanha(yi.y);
    float sfx = 0.5f + 0.5f * tanha(yf.x), sfy = 0.5f + 0.5f * tanha(yf.y);
    float tgx = tanha(yg.x), tgy = tanha(yg.y);
    float sox = 0.5f + 0.5f * tanha(yo.x), soy = 0.5f + 0.5f * tanha(yo.y);
    c.x = sfx * c.x + six * tgx;
    c.y = sfy * c.y + siy * tgy;
    h.x = sox * tanha(c.x);
    h.y = soy * tanha(c.y);
}

// ---------------- weight prep (interleaved [k][up][gate][2], 0.5 prescale on i/f/o) ----------------
__global__ void prep1(const float* wfih, const float* wfhh, const float* bfih, const float* bfhh,
                      const float* wbih, const float* wbhh, const float* bbih, const float* bbhh) {
    int idx = blockIdx.x * blockDim.x + threadIdx.x;
    if (idx < 2 * 80 * 280) {
        int d = idx / 22400, rem = idx % 22400;
        int k = rem / 280, j = rem % 280;
        int up = j / 8, g = (j / 2) % 4, e = j & 1;
        int u = up * 2 + e, row = g * 70 + u;
        const float* wih = d ? wbih : wfih;
        const float* whh = d ? wbhh : wfhh;
        float v = (k < 10) ? wih[row * 10 + k] : whh[row * 70 + (k - 10)];
        if (g != 2) v *= 0.5f;
        dW1g[idx] = v;
    }
    if (idx < 2 * 280) {
        int d = idx / 280, j = idx % 280;
        int up = j / 8, g = (j / 2) % 4, e = j & 1;
        int u = up * 2 + e, row = g * 70 + u;
        const float* bih = d ? bbih : bfih;
        const float* bhh = d ? bbhh : bfhh;
        float v = bih[row] + bhh[row];
        if (g != 2) v *= 0.5f;
        dB1g[idx] = v;
    }
}

__global__ void prep2(const float* wfih, const float* wfhh, const float* bfih, const float* bfhh,
                      const float* wbih, const float* wbhh, const float* bbih, const float* bbhh) {
    int idx = blockIdx.x * blockDim.x + threadIdx.x;
    if (idx < 2 * 161 * 88) {
        int d = idx / (161 * 88), rem = idx % (161 * 88);
        int k = rem / 88, j = rem % 88;
        int up = j / 8, g = (j / 2) % 4, e = j & 1;
        int u = up * 2 + e;
        float v = 0.f;
        if (u < 21) {
            int row = g * 21 + u;
            const float* wih = d ? wbih : wfih;
            const float* whh = d ? wbhh : wfhh;
            v = (k < 140) ? wih[row * 140 + k] : whh[row * 21 + (k - 140)];
            if (g != 2) v *= 0.5f;
        }
        dW2g[idx] = v;
    }
    if (idx < 2 * 88) {
        int d = idx / 88, j = idx % 88;
        int up = j / 8, g = (j / 2) % 4, e = j & 1;
        int u = up * 2 + e;
        float v = 0.f;
        if (u < 21) {
            int row = g * 21 + u;
            const float* bih = d ? bbih : bfih;
            const float* bhh = d ? bbhh : bfhh;
            v = bih[row] + bhh[row];
            if (g != 2) v *= 0.5f;
        }
        dB2g[idx] = v;
    }
}

// ---------------- layer 1: F=10 -> H=70, bidirectional ----------------
// grid (64, 2), 280 threads, WARP-MAJOR over rows: tid = rg + 8*up.
// A warp holds 4 unit-pairs x 8 rowgroups -> weight LDS.128 is a 4-address
// broadcast (1 wavefront); activation loads are contiguous (1-2 wavefronts).
// Thread owns 4 rows x 2 units x 4 gates. Double-buffered activations,
// one __syncthreads per step.
#define SA1 5440   // one act buffer: 80 k * 68 floats (32 rows duplicated + pad)
__global__ __launch_bounds__(280, 1) void lstm1(const float* __restrict__ x) {
    extern __shared__ float sm[];
    float* sW = sm;                 // 22400
    float* sB = sW + 22400;         // 280
    float* sA = sB + 280;           // 2 * SA1
    const int dir = blockIdx.y, bblk = blockIdx.x;
    const int b0 = bblk * 32;
    const int tid = threadIdx.x;

    const float* gW = dW1g + dir * 22400;
    for (int i = tid; i < 22400; i += 280) sW[i] = gW[i];
    sB[tid] = dB1g[dir * 280 + tid];
    // zero h-region of buffer 0 only (x-region fully staged below)
    for (int i = tid; i < 70 * 68; i += 280) sA[10 * 68 + i] = 0.f;

    // stage x(t0) into buffer 0 (each thread covers i and maybe i+280 of 320)
    const int xrow0 = tid / 10, xf0 = tid % 10;
    const int i1 = tid + 280;
    const bool has1 = i1 < 320;
    const int xrow1 = i1 / 10, xf1 = i1 % 10;
    {
        int t0 = dir ? TT - 1 : 0;
        *(ull*)&sA[xf0 * 68 + 2 * xrow0] = pk2(x[((b0 + xrow0) * TT + t0) * 10 + xf0]);
        if (has1)
            *(ull*)&sA[xf1 * 68 + 2 * xrow1] = pk2(x[((b0 + xrow1) * TT + t0) * 10 + xf1]);
    }

    const int rg = tid & 7, up = tid >> 3;
    const int u0 = up * 2, r0 = rg * 4;
    const float* pw = sW + up * 8;
    float2 c[4];
#pragma unroll
    for (int r = 0; r < 4; r++) c[r] = make_float2(0.f, 0.f);

    // prefetch x(t1)
    float xr0 = 0.f, xr1 = 0.f;
    {
        int t1 = dir ? TT - 2 : 1;
        xr0 = x[((b0 + xrow0) * TT + t1) * 10 + xf0];
        if (has1) xr1 = x[((b0 + xrow1) * TT + t1) * 10 + xf1];
    }
    __syncthreads();

    // bias packs: read AFTER the barrier (cross-thread sB ordering is now guaranteed)
    ull bp[4];
#pragma unroll
    for (int g = 0; g < 4; g++) bp[g] = *(const ull*)&sB[up * 8 + g * 2];

    int p = 0;
    for (int s = 0; s < TT; s++) {
        const int t = dir ? TT - 1 - s : s;
        const float* pa = sA + p * SA1 + 2 * r0;

        ull acc[4][4];
#pragma unroll
        for (int r = 0; r < 4; r++)
#pragma unroll
            for (int g = 0; g < 4; g++) acc[r][g] = bp[g];

#pragma unroll 8
        for (int k = 0; k < 80; k++) {
            ulonglong2 a01 = *(const ulonglong2*)(pa + k * 68);       // {v0,v0},{v1,v1}
            ulonglong2 a23 = *(const ulonglong2*)(pa + k * 68 + 4);   // {v2,v2},{v3,v3}
            ulonglong2 w01 = *(const ulonglong2*)(pw + k * 280);      // gate pairs 0,1 (bcast)
            ulonglong2 w23 = *(const ulonglong2*)(pw + k * 280 + 4);  // gate pairs 2,3 (bcast)
            fma2(acc[0][0], a01.x, w01.x); fma2(acc[0][1], a01.x, w01.y);
            fma2(acc[0][2], a01.x, w23.x); fma2(acc[0][3], a01.x, w23.y);
            fma2(acc[1][0], a01.y, w01.x); fma2(acc[1][1], a01.y, w01.y);
            fma2(acc[1][2], a01.y, w23.x); fma2(acc[1][3], a01.y, w23.y);
            fma2(acc[2][0], a23.x, w01.x); fma2(acc[2][1], a23.x, w01.y);
            fma2(acc[2][2], a23.x, w23.x); fma2(acc[2][3], a23.x, w23.y);
            fma2(acc[3][0], a23.y, w01.x); fma2(acc[3][1], a23.y, w01.y);
            fma2(acc[3][2], a23.y, w23.x); fma2(acc[3][3], a23.y, w23.y);
        }

        float2 hv[4];
#pragma unroll
        for (int r = 0; r < 4; r++) {
            lstm_act(up2(acc[r][0]), up2(acc[r][1]), up2(acc[r][2]), up2(acc[r][3]),
                     c[r], hv[r]);
        }

        // write h(t) into other buffer (input for t+1)
        float* nb = sA + (p ^ 1) * SA1;
#pragma unroll
        for (int r = 0; r < 4; r++) {
            *(ull*)&nb[(10 + u0) * 68 + 2 * (r0 + r)] = pk2(hv[r].x);
            *(ull*)&nb[(11 + u0) * 68 + 2 * (r0 + r)] = pk2(hv[r].y);
        }
        // stage x(t+1) into other buffer
        if (s + 1 < TT) {
            *(ull*)&nb[xf0 * 68 + 2 * xrow0] = pk2(xr0);
            if (has1) *(ull*)&nb[xf1 * 68 + 2 * xrow1] = pk2(xr1);
        }
        // global h1 (blocked-transposed): 2 x STG.128
        {
            size_t gb = ((size_t)(bblk * TT + t) * 140 + dir * 70 + u0) * 32 + r0;
            *(float4*)&dH1T[gb]      = make_float4(hv[0].x, hv[1].x, hv[2].x, hv[3].x);
            *(float4*)&dH1T[gb + 32] = make_float4(hv[0].y, hv[1].y, hv[2].y, hv[3].y);
        }
        // prefetch x(t+2)
        if (s + 2 < TT) {
            int tn = dir ? TT - 3 - s : s + 2;
            xr0 = x[((b0 + xrow0) * TT + tn) * 10 + xf0];
            if (has1) xr1 = x[((b0 + xrow1) * TT + tn) * 10 + xf1];
        }
        __syncthreads();
        p ^= 1;
    }
}

// ---------------- layer 2: 140 -> H=21 (pad 22), bidirectional ----------------
// grid (64, 2), 176 threads, WARP-MAJOR over rows: tid = rg + 16*up.
// Warp holds 2 unit-pairs x 16 rowgroups -> weight LDS.128 is a 2-address
// broadcast. Thread owns 2 rows x 2 units x 4 gates.
#define SA2 10948  // one act buffer: 161 k * 68 floats
__global__ __launch_bounds__(176, 1) void lstm2() {
    extern __shared__ float sm[];
    float* sW = sm;                  // 161*88 = 14168
    float* sB = sW + 14168;          // 88
    float* sA = sB + 88;             // 2 * SA2
    const int dir = blockIdx.y, bblk = blockIdx.x;
    const int b0 = bblk * 32;
    const int tid = threadIdx.x;

    const float* gW = dW2g + dir * 14168;
    for (int i = tid; i < 14168; i += 176) sW[i] = gW[i];
    if (tid < 88) sB[tid] = dB2g[dir * 88 + tid];
    for (int i = tid; i < 21 * 68; i += 176) sA[140 * 68 + i] = 0.f;

    // stage h1(t0) into buffer 0: 1120 float4 loads, 7 per thread
    {
        int t0 = dir ? TT - 1 : 0;
        size_t gb = (size_t)(bblk * TT + t0) * 4480;
#pragma unroll
        for (int j = 0; j < 7; j++) {
            int i = tid + j * 176;
            if (i < 1120) {
                float4 v = *(const float4*)&dH1T[gb + (size_t)i * 4];
                int k = i >> 3, rq = i & 7;
                float* d = sA + k * 68 + 8 * rq;
                *(ull*)(d + 0) = pk2(v.x);
                *(ull*)(d + 2) = pk2(v.y);
                *(ull*)(d + 4) = pk2(v.z);
                *(ull*)(d + 6) = pk2(v.w);
            }
        }
    }

    const int rg = tid & 15, up = tid >> 4;
    const int u0 = up * 2, r0 = rg * 2;
    const float* pw = sW + up * 8;
    float2 c[2];
    c[0] = make_float2(0.f, 0.f);
    c[1] = make_float2(0.f, 0.f);

    // prefetch h1(t1)
    float4 pf[7];
    {
        int t1 = dir ? TT - 2 : 1;
        size_t gb = (size_t)(bblk * TT + t1) * 4480;
#pragma unroll
        for (int j = 0; j < 7; j++) {
            int i = tid + j * 176;
            if (i < 1120) pf[j] = *(const float4*)&dH1T[gb + (size_t)i * 4];
        }
    }
    __syncthreads();

    // bias packs: read AFTER the barrier. Before the fix, warps 2-5 read words
    // written by warps 1-2 with no intervening barrier; the hi-wid-first arbiter
    // let high warps race ahead -> systematically stale biases (R6's 2e-2 error).
    ull bp[4];
#pragma unroll
    for (int g = 0; g < 4; g++) bp[g] = *(const ull*)&sB[up * 8 + g * 2];

    int p = 0;
    for (int s = 0; s < TT; s++) {
        const int t = dir ? TT - 1 - s : s;
        const float* pa = sA + p * SA2 + 2 * r0;

        ull acc[2][4];
#pragma unroll
        for (int r = 0; r < 2; r++)
#pragma unroll
            for (int g = 0; g < 4; g++) acc[r][g] = bp[g];

#pragma unroll 7
        for (int k = 0; k < 161; k++) {
            ulonglong2 a = *(const ulonglong2*)(pa + k * 68);        // {v0,v0},{v1,v1}
            ulonglong2 w01 = *(const ulonglong2*)(pw + k * 88);      // bcast
            ulonglong2 w23 = *(const ulonglong2*)(pw + k * 88 + 4);  // bcast
            fma2(acc[0][0], a.x, w01.x); fma2(acc[0][1], a.x, w01.y);
            fma2(acc[0][2], a.x, w23.x); fma2(acc[0][3], a.x, w23.y);
            fma2(acc[1][0], a.y, w01.x); fma2(acc[1][1], a.y, w01.y);
            fma2(acc[1][2], a.y, w23.x); fma2(acc[1][3], a.y, w23.y);
        }

        float2 hv[2];
#pragma unroll
        for (int r = 0; r < 2; r++) {
            lstm_act(up2(acc[r][0]), up2(acc[r][1]), up2(acc[r][2]), up2(acc[r][3]),
                     c[r], hv[r]);
        }

        float* nb = sA + (p ^ 1) * SA2;
#pragma unroll
        for (int r = 0; r < 2; r++) {
            *(ull*)&nb[(140 + u0) * 68 + 2 * (r0 + r)] = pk2(hv[r].x);
            if (u0 + 1 < 21)
                *(ull*)&nb[(141 + u0) * 68 + 2 * (r0 + r)] = pk2(hv[r].y);
            size_t ob = (size_t)((b0 + r0 + r) * TT + t) * 42 + dir * 21 + u0;
            dH2[ob] = hv[r].x;
            if (u0 + 1 < 21) dH2[ob + 1] = hv[r].y;
        }

        // stage h1(t+1) into other buffer
        if (s + 1 < TT) {
#pragma unroll
            for (int j = 0; j < 7; j++) {
                int i = tid + j * 176;
                if (i < 1120) {
                    int k = i >> 3, rq = i & 7;
                    float* d = nb + k * 68 + 8 * rq;
                    *(ull*)(d + 0) = pk2(pf[j].x);
                    *(ull*)(d + 2) = pk2(pf[j].y);
                    *(ull*)(d + 4) = pk2(pf[j].z);
                    *(ull*)(d + 6) = pk2(pf[j].w);
                }
            }
        }
        // prefetch h1(t+2)
        if (s + 2 < TT) {
            int tn = dir ? TT - 3 - s : s + 2;
            size_t gb = (size_t)(bblk * TT + tn) * 4480;
#pragma unroll
            for (int j = 0; j < 7; j++) {
                int i = tid + j * 176;
                if (i < 1120) pf[j] = *(const float4*)&dH1T[gb + (size_t)i * 4];
            }
        }
        __syncthreads();
        p ^= 1;
    }
}

// ---------------- dense head: 42 -> relu 30 -> relu 20 -> 1 ----------------
__global__ __launch_bounds__(256) void dense_head(const float* __restrict__ wd1, const float* __restrict__ bd1,
                                                  const float* __restrict__ wd2, const float* __restrict__ bd2,
                                                  const float* __restrict__ wo, const float* __restrict__ bo,
                                                  float* __restrict__ out) {
    __shared__ float sW1[30 * 42], sb1[30], sW2[20 * 30], sb2[20], swo[20], sbo[1];
    int tid = threadIdx.x;
    for (int i = tid; i < 1260; i += 256) sW1[i] = wd1[i];
    for (int i = tid; i < 600; i += 256) sW2[i] = wd2[i];
    if (tid < 30) sb1[tid] = bd1[tid];
    if (tid < 20) { sb2[tid] = bd2[tid]; swo[tid] = wo[tid]; }
    if (tid == 0) sbo[0] = bo[0];
    __syncthreads();

    int pos = blockIdx.x * 256 + tid;
    float in[42];
    const float* p = dH2 + (size_t)pos * 42;
#pragma unroll
    for (int k = 0; k < 42; k++) in[k] = p[k];

    float a[30];
#pragma unroll
    for (int j = 0; j < 30; j++) {
        float s = sb1[j];
#pragma unroll
        for (int k = 0; k < 42; k++) s += in[k] * sW1[j * 42 + k];
        a[j] = fmaxf(s, 0.f);
    }
    float o = sbo[0];
#pragma unroll
    for (int j = 0; j < 20; j++) {
        float s = sb2[j];
#pragma unroll
        for (int k = 0; k < 30; k++) s += a[k] * sW2[j * 30 + k];
        o += fmaxf(s, 0.f) * swo[j];
    }
    out[pos] = o;
}

// ---------------- launch ----------------
extern "C" void kernel_launch(void* const* d_in, const int* in_sizes, int n_in,
                              void* d_out, int out_size) {
    const float* x = (const float*)d_in[0];

    const int smem1 = (22400 + 280 + 2 * SA1) * 4;   // 134240 B
    const int smem2 = (14168 + 88 + 2 * SA2) * 4;    // 144608 B
    cudaFuncSetAttribute(lstm1, cudaFuncAttributeMaxDynamicSharedMemorySize, smem1);
    cudaFuncSetAttribute(lstm2, cudaFuncAttributeMaxDynamicSharedMemorySize, smem2);

    prep1<<<175, 256>>>((const float*)d_in[1], (const float*)d_in[2], (const float*)d_in[3], (const float*)d_in[4],
                        (const float*)d_in[5], (const float*)d_in[6], (const float*)d_in[7], (const float*)d_in[8]);
    prep2<<<111, 256>>>((const float*)d_in[9], (const float*)d_in[10], (const float*)d_in[11], (const float*)d_in[12],
                        (const float*)d_in[13], (const float*)d_in[14], (const float*)d_in[15], (const float*)d_in[16]);

    lstm1<<<dim3(64, 2), 280, smem1>>>(x);
    lstm2<<<dim3(64, 2), 176, smem2>>>();

    dense_head<<<(2048 * 336) / 256, 256>>>((const float*)d_in[17], (const float*)d_in[18],
                                            (const float*)d_in[19], (const float*)d_in[20],
                                            (const float*)d_in[21], (const float*)d_in[22],
                                            (float*)d_out);
}

// round 10
// speedup vs baseline: 2.2970x; 1.3923x over previous
#include <cuda_runtime.h>

#define TT 336

// ---------------- device scratch ----------------
__device__ float dW1g[2 * 80 * 280];        // [dir][k][up(35)][gate(4)][2], i/f/o prescaled 0.5
__device__ float dB1g[2 * 280];             // [dir][up][gate][2]
__device__ float dW2g[2 * 161 * 88];        // [dir][k][up(11)][gate(4)][2]
__device__ float dB2g[2 * 88];
__device__ float dH1T[64 * 336 * 140 * 32]; // [bblk][t][k(140)][r(32)]
__device__ float dH2[64 * 336 * 42 * 32];   // [bblk][t][u(42)][r(32)]

typedef unsigned long long ull;

// ---------------- f32x2 helpers ----------------
__device__ __forceinline__ ull pk2(float v) {
    ull r;
    asm("mov.b64 %0, {%1, %1};" : "=l"(r) : "f"(v));
    return r;
}
__device__ __forceinline__ float2 up2(ull v) {
    float2 r;
    asm("mov.b64 {%0, %1}, %2;" : "=f"(r.x), "=f"(r.y) : "l"(v));
    return r;
}
__device__ __forceinline__ void fma2(ull& d, ull a, ull b) {
    asm("fma.rn.f32x2 %0, %1, %2, %3;" : "=l"(d) : "l"(a), "l"(b), "l"(d));
}
__device__ __forceinline__ float tanha(float x) {
    float y;
    asm("tanh.approx.f32 %0, %1;" : "=f"(y) : "f"(x));
    return y;
}
// i/f/o pre-acts prescaled by 0.5 -> sigmoid(z) = 0.5 + 0.5*tanh(z/2)
__device__ __forceinline__ void lstm_act(float2 yi, float2 yf, float2 yg, float2 yo,
                                         float2& c, float2& h) {
    float six = 0.5f + 0.5f * tanha(yi.x), siy = 0.5f + 0.5f * tanha(yi.y);
    float sfx = 0.5f + 0.5f * tanha(yf.x), sfy = 0.5f + 0.5f * tanha(yf.y);
    float tgx = tanha(yg.x), tgy = tanha(yg.y);
    float sox = 0.5f + 0.5f * tanha(yo.x), soy = 0.5f + 0.5f * tanha(yo.y);
    c.x = sfx * c.x + six * tgx;
    c.y = sfy * c.y + siy * tgy;
    h.x = sox * tanha(c.x);
    h.y = soy * tanha(c.y);
}

// ---------------- weight prep (interleaved [k][up][gate][2], 0.5 prescale on i/f/o) ----------------
__global__ void prep1(const float* wfih, const float* wfhh, const float* bfih, const float* bfhh,
                      const float* wbih, const float* wbhh, const float* bbih, const float* bbhh) {
    int idx = blockIdx.x * blockDim.x + threadIdx.x;
    if (idx < 2 * 80 * 280) {
        int d = idx / 22400, rem = idx % 22400;
        int k = rem / 280, j = rem % 280;
        int up = j / 8, g = (j / 2) % 4, e = j & 1;
        int u = up * 2 + e, row = g * 70 + u;
        const float* wih = d ? wbih : wfih;
        const float* whh = d ? wbhh : wfhh;
        float v = (k < 10) ? wih[row * 10 + k] : whh[row * 70 + (k - 10)];
        if (g != 2) v *= 0.5f;
        dW1g[idx] = v;
    }
    if (idx < 2 * 280) {
        int d = idx / 280, j = idx % 280;
        int up = j / 8, g = (j / 2) % 4, e = j & 1;
        int u = up * 2 + e, row = g * 70 + u;
        const float* bih = d ? bbih : bfih;
        const float* bhh = d ? bbhh : bfhh;
        float v = bih[row] + bhh[row];
        if (g != 2) v *= 0.5f;
        dB1g[idx] = v;
    }
}

__global__ void prep2(const float* wfih, const float* wfhh, const float* bfih, const float* bfhh,
                      const float* wbih, const float* wbhh, const float* bbih, const float* bbhh) {
    int idx = blockIdx.x * blockDim.x + threadIdx.x;
    if (idx < 2 * 161 * 88) {
        int d = idx / (161 * 88), rem = idx % (161 * 88);
        int k = rem / 88, j = rem % 88;
        int up = j / 8, g = (j / 2) % 4, e = j & 1;
        int u = up * 2 + e;
        float v = 0.f;
        if (u < 21) {
            int row = g * 21 + u;
            const float* wih = d ? wbih : wfih;
            const float* whh = d ? wbhh : wfhh;
            v = (k < 140) ? wih[row * 140 + k] : whh[row * 21 + (k - 140)];
            if (g != 2) v *= 0.5f;
        }
        dW2g[idx] = v;
    }
    if (idx < 2 * 88) {
        int d = idx / 88, j = idx % 88;
        int up = j / 8, g = (j / 2) % 4, e = j & 1;
        int u = up * 2 + e;
        float v = 0.f;
        if (u < 21) {
            int row = g * 21 + u;
            const float* bih = d ? bbih : bfih;
            const float* bhh = d ? bbhh : bfhh;
            v = bih[row] + bhh[row];
            if (g != 2) v *= 0.5f;
        }
        dB2g[idx] = v;
    }
}

// ---------------- layer 1: F=10 -> H=70, bidirectional ----------------
// grid (64, 2), 560 threads = 2 k-groups x 280 (rg 0..7 [4 rows] x up 0..34).
// Non-duplicated acts [k][r32]: act load = 1x LDS.128 (1 wf), dup via MOV (ALU).
// Thread accumulates 4 rows x 2 units x 4 gates over its 40-k half, exchanges
// the non-owned 2-row half via coalesced SMEM, finalizes 2 rows.
__global__ __launch_bounds__(560, 1) void lstm1(const float* __restrict__ x) {
    extern __shared__ float sm[];
    float* sW = sm;                  // 22400
    float* sB = sW + 22400;          // 280
    float* sA = sB + 280;            // 2 * 2560  ([k80][r32] per buffer)
    float* sRed = sA + 5120;         // 2 grp * 8 j * 280 q * 2 = 8960
    const int dir = blockIdx.y, bblk = blockIdx.x;
    const int b0 = bblk * 32;
    const int tid = threadIdx.x;

    const float* gW = dW1g + dir * 22400;
    for (int i = tid; i < 22400; i += 560) sW[i] = gW[i];
    if (tid < 280) sB[tid] = dB1g[dir * 280 + tid];
    for (int i = tid; i < 70 * 32; i += 560) sA[10 * 32 + i] = 0.f;   // h-region buf0

    const int grp = (tid >= 280) ? 1 : 0;
    const int q = tid - 280 * grp;
    const int rg = q & 7, up = q >> 3;
    const int r0 = rg * 4, u0 = up * 2;
    const int rown = r0 + 2 * grp;   // owned rows: rown, rown+1
    const int jo = 2 * grp;          // owned acc idx
    const int jn = 2 - 2 * grp;      // non-owned acc idx

    // stage x(t0) into buffer 0 (non-dup: 1 float per thread, tid<320)
    const int xrow = tid / 10, xf = tid % 10;
    const bool hasx = tid < 320;
    if (hasx) sA[xf * 32 + xrow] = x[((b0 + xrow) * TT + (dir ? TT - 1 : 0)) * 10 + xf];
    float xr = 0.f;
    if (hasx) xr = x[((b0 + xrow) * TT + (dir ? TT - 2 : 1)) * 10 + xf];

    float2 c[2];
    c[0] = make_float2(0.f, 0.f);
    c[1] = make_float2(0.f, 0.f);
    const float* pw = sW + grp * 40 * 280 + up * 8;
    float* sRW = sRed + grp * 8 * 560;            // write: [j][q][2]
    const float* sRR = sRed + (1 - grp) * 8 * 560;
    __syncthreads();

    float2 bf[4];
#pragma unroll
    for (int g = 0; g < 4; g++) bf[g] = *(const float2*)&sB[up * 8 + g * 2];

    int p = 0;
    for (int s = 0; s < TT; s++) {
        const int t = dir ? TT - 1 - s : s;
        // FIX (R9 bug): activation pointer must carry the k-group offset too;
        // grp1 was multiplying weights k=40..79 against acts k=0..39.
        const float* pa = sA + p * 2560 + grp * 1280 + r0;

        ull acc[4][4];
#pragma unroll
        for (int r = 0; r < 4; r++)
#pragma unroll
            for (int g = 0; g < 4; g++) acc[r][g] = 0ull;

#pragma unroll 8
        for (int k = 0; k < 40; k++) {
            float4 av = *(const float4*)(pa + k * 32);          // rows r0..r0+3 (1 wf)
            ull a0 = pk2(av.x), a1 = pk2(av.y), a2 = pk2(av.z), a3 = pk2(av.w);
            ulonglong2 w01 = *(const ulonglong2*)(pw + k * 280);       // gates 0,1 (bcast)
            ulonglong2 w23 = *(const ulonglong2*)(pw + k * 280 + 4);   // gates 2,3 (bcast)
            fma2(acc[0][0], a0, w01.x); fma2(acc[0][1], a0, w01.y);
            fma2(acc[0][2], a0, w23.x); fma2(acc[0][3], a0, w23.y);
            fma2(acc[1][0], a1, w01.x); fma2(acc[1][1], a1, w01.y);
            fma2(acc[1][2], a1, w23.x); fma2(acc[1][3], a1, w23.y);
            fma2(acc[2][0], a2, w01.x); fma2(acc[2][1], a2, w01.y);
            fma2(acc[2][2], a2, w23.x); fma2(acc[2][3], a2, w23.y);
            fma2(acc[3][0], a3, w01.x); fma2(acc[3][1], a3, w01.y);
            fma2(acc[3][2], a3, w23.x); fma2(acc[3][3], a3, w23.y);
        }

        // write non-owned 2-row partials (coalesced [j][q] layout, 2 wf/instr)
#pragma unroll
        for (int j = 0; j < 8; j++)
            *(ull*)&sRW[j * 560 + q * 2] = acc[jn + (j >> 2)][j & 3];
        __syncthreads();

        float2 hv[2];
#pragma unroll
        for (int jj = 0; jj < 2; jj++) {
            float2 y[4];
#pragma unroll
            for (int g = 0; g < 4; g++) {
                float2 own = up2(acc[jo + jj][g]);
                float2 pe = up2(*(const ull*)&sRR[(jj * 4 + g) * 560 + q * 2]);
                y[g] = make_float2(own.x + pe.x + bf[g].x, own.y + pe.y + bf[g].y);
            }
            lstm_act(y[0], y[1], y[2], y[3], c[jj], hv[jj]);
        }

        // h(t) -> other buffer (non-dup) + global blocked-transposed
        float* nb = sA + (p ^ 1) * 2560;
        *(float2*)&nb[(10 + u0) * 32 + rown] = make_float2(hv[0].x, hv[1].x);
        *(float2*)&nb[(11 + u0) * 32 + rown] = make_float2(hv[0].y, hv[1].y);
        {
            size_t gb = ((size_t)(bblk * TT + t) * 140 + dir * 70 + u0) * 32 + rown;
            *(float2*)&dH1T[gb]      = make_float2(hv[0].x, hv[1].x);
            *(float2*)&dH1T[gb + 32] = make_float2(hv[0].y, hv[1].y);
        }
        // stage x(t+1) + prefetch x(t+2)
        if (hasx) {
            nb[xf * 32 + xrow] = xr;
            if (s + 2 < TT) {
                int tn = dir ? TT - 3 - s : s + 2;
                xr = x[((b0 + xrow) * TT + tn) * 10 + xf];
            }
        }
        __syncthreads();
        p ^= 1;
    }
}

// ---------------- layer 2: 140 -> H=21 (pad 22), bidirectional ----------------
// grid (64, 2), 352 threads = 2 k-groups x 176 (rg 0..15 [2 rows] x up 0..10).
// Non-dup acts [k][r32]; act = LDS.64 (1 wf) + 2 MOV; weights 2x LDS.128 bcast.
// Thread accumulates 2 rows x 2 units x 4 gates over its 80/81-k half,
// exchanges the non-owned row, finalizes 1 row.
#define L2_KLOOP(KN)                                                          \
    _Pragma("unroll 8")                                                       \
    for (int k = 0; k < (KN); k++) {                                          \
        float2 av = *(const float2*)(pa + k * 32);                            \
        ull a0 = pk2(av.x), a1 = pk2(av.y);                                   \
        ulonglong2 w01 = *(const ulonglong2*)(pw + k * 88);                   \
        ulonglong2 w23 = *(const ulonglong2*)(pw + k * 88 + 4);               \
        fma2(acc[0][0], a0, w01.x); fma2(acc[0][1], a0, w01.y);               \
        fma2(acc[0][2], a0, w23.x); fma2(acc[0][3], a0, w23.y);               \
        fma2(acc[1][0], a1, w01.x); fma2(acc[1][1], a1, w01.y);               \
        fma2(acc[1][2], a1, w23.x); fma2(acc[1][3], a1, w23.y);               \
    }

__global__ __launch_bounds__(352, 1) void lstm2() {
    extern __shared__ float sm[];
    float* sW = sm;                  // 14168
    float* sB = sW + 14168;          // 88
    float* sA = sB + 88;             // 2 * 5152  ([k161][r32] per buffer)
    float* sRed = sA + 10304;        // 2 grp * 4 g * 176 q * 2 = 2816
    const int dir = blockIdx.y, bblk = blockIdx.x;
    const int b0 = bblk * 32;
    const int tid = threadIdx.x;

    const float* gW = dW2g + dir * 14168;
    for (int i = tid; i < 14168; i += 352) sW[i] = gW[i];
    if (tid < 88) sB[tid] = dB2g[dir * 88 + tid];
    for (int i = tid; i < 21 * 32; i += 352) sA[140 * 32 + i] = 0.f;   // h-region buf0

    // stage h1(t0): 1120 float4, straight contiguous copy
    {
        int t0 = dir ? TT - 1 : 0;
        const float4* src = (const float4*)&dH1T[(size_t)(bblk * TT + t0) * 4480];
        float4* dst = (float4*)sA;
#pragma unroll
        for (int j = 0; j < 4; j++) {
            int i = tid + j * 352;
            if (i < 1120) dst[i] = src[i];
        }
    }

    const int grp = (tid >= 176) ? 1 : 0;
    const int q = tid - 176 * grp;
    const int rg = q & 15, up = q >> 4;
    const int r0 = rg * 2, u0 = up * 2;
    const int rown = r0 + grp;       // owned row
    const int jo = grp, jn = 1 - grp;

    float2 c = make_float2(0.f, 0.f);
    const int kbeg = grp * 80;
    const float* pw = sW + kbeg * 88 + up * 8;
    float* sRW = sRed + grp * 4 * 352;
    const float* sRR = sRed + (1 - grp) * 4 * 352;

    // prefetch h1(t1)
    float4 pf[4];
    {
        int t1 = dir ? TT - 2 : 1;
        const float4* src = (const float4*)&dH1T[(size_t)(bblk * TT + t1) * 4480];
#pragma unroll
        for (int j = 0; j < 4; j++) {
            int i = tid + j * 352;
            if (i < 1120) pf[j] = src[i];
        }
    }
    __syncthreads();

    float2 bf[4];
#pragma unroll
    for (int g = 0; g < 4; g++) bf[g] = *(const float2*)&sB[up * 8 + g * 2];

    int p = 0;
    for (int s = 0; s < TT; s++) {
        const int t = dir ? TT - 1 - s : s;
        const float* pa = sA + p * 5152 + kbeg * 32 + r0;

        ull acc[2][4];
#pragma unroll
        for (int r = 0; r < 2; r++)
#pragma unroll
            for (int g = 0; g < 4; g++) acc[r][g] = 0ull;

        if (grp == 0) { L2_KLOOP(80) } else { L2_KLOOP(81) }

        // write non-owned row partials (coalesced)
#pragma unroll
        for (int g = 0; g < 4; g++)
            *(ull*)&sRW[g * 352 + q * 2] = acc[jn][g];
        __syncthreads();

        float2 y[4];
#pragma unroll
        for (int g = 0; g < 4; g++) {
            float2 own = up2(acc[jo][g]);
            float2 pe = up2(*(const ull*)&sRR[g * 352 + q * 2]);
            y[g] = make_float2(own.x + pe.x + bf[g].x, own.y + pe.y + bf[g].y);
        }
        float2 h;
        lstm_act(y[0], y[1], y[2], y[3], c, h);

        // h -> other buffer + global dH2 [bblk][t][42][r32] (coalesced)
        float* nb = sA + (p ^ 1) * 5152;
        nb[(140 + u0) * 32 + rown] = h.x;
        if (u0 + 1 < 21) nb[(141 + u0) * 32 + rown] = h.y;
        {
            size_t ob = ((size_t)(bblk * TT + t) * 42 + dir * 21 + u0) * 32 + rown;
            dH2[ob] = h.x;
            if (u0 + 1 < 21) dH2[ob + 32] = h.y;
        }

        // stage h1(t+1) into other buffer (contiguous STS.128)
        if (s + 1 < TT) {
            float4* dst = (float4*)nb;
#pragma unroll
            for (int j = 0; j < 4; j++) {
                int i = tid + j * 352;
                if (i < 1120) dst[i] = pf[j];
            }
        }
        // prefetch h1(t+2)
        if (s + 2 < TT) {
            int tn = dir ? TT - 3 - s : s + 2;
            const float4* src = (const float4*)&dH1T[(size_t)(bblk * TT + tn) * 4480];
#pragma unroll
            for (int j = 0; j < 4; j++) {
                int i = tid + j * 352;
                if (i < 1120) pf[j] = src[i];
            }
        }
        __syncthreads();
        p ^= 1;
    }
}

// ---------------- dense head: 42 -> relu 30 -> relu 20 -> 1 ----------------
// grid (64, 84): CTA = (bblk, 4-t tile). Stages the [4t][42u][32r] tile through
// SMEM (coalesced LDG + coalesced LDS), 128 threads = one position each.
__global__ __launch_bounds__(128) void dense_head(const float* __restrict__ wd1, const float* __restrict__ bd1,
                                                  const float* __restrict__ wd2, const float* __restrict__ bd2,
                                                  const float* __restrict__ wo, const float* __restrict__ bo,
                                                  float* __restrict__ out) {
    __shared__ float sT[4 * 42 * 32];
    __shared__ float sW1[30 * 42], sb1[30], sW2[20 * 30], sb2[20], swo[20], sbo[1];
    const int tid = threadIdx.x;
    const int bblk = blockIdx.x, t0 = blockIdx.y * 4;

    {
        const float4* src = (const float4*)&dH2[(size_t)(bblk * TT + t0) * 1344];
        float4* dst = (float4*)sT;
#pragma unroll
        for (int j = 0; j < 11; j++) {
            int i = tid + j * 128;
            if (i < 1344) dst[i] = src[i];
        }
    }
    for (int i = tid; i < 1260; i += 128) sW1[i] = wd1[i];
    for (int i = tid; i < 600; i += 128) sW2[i] = wd2[i];
    if (tid < 30) sb1[tid] = bd1[tid];
    if (tid < 20) { sb2[tid] = bd2[tid]; swo[tid] = wo[tid]; }
    if (tid == 0) sbo[0] = bo[0];
    __syncthreads();

    const int t = tid >> 5, r = tid & 31;
    float in[42];
#pragma unroll
    for (int u = 0; u < 42; u++) in[u] = sT[(t * 42 + u) * 32 + r];

    float a[30];
#pragma unroll
    for (int j = 0; j < 30; j++) {
        float s = sb1[j];
#pragma unroll
        for (int k = 0; k < 42; k++) s += in[k] * sW1[j * 42 + k];
        a[j] = fmaxf(s, 0.f);
    }
    float o = sbo[0];
#pragma unroll
    for (int j = 0; j < 20; j++) {
        float s = sb2[j];
#pragma unroll
        for (int k = 0; k < 30; k++) s += a[k] * sW2[j * 30 + k];
        o += fmaxf(s, 0.f) * swo[j];
    }
    out[(size_t)(bblk * 32 + r) * TT + t0 + t] = o;
}

// ---------------- launch ----------------
extern "C" void kernel_launch(void* const* d_in, const int* in_sizes, int n_in,
                              void* d_out, int out_size) {
    const float* x = (const float*)d_in[0];

    const int smem1 = (22400 + 280 + 2 * 2560 + 8960) * 4;   // 147040 B
    const int smem2 = (14168 + 88 + 2 * 5152 + 2816) * 4;    // 109504 B
    cudaFuncSetAttribute(lstm1, cudaFuncAttributeMaxDynamicSharedMemorySize, smem1);
    cudaFuncSetAttribute(lstm2, cudaFuncAttributeMaxDynamicSharedMemorySize, smem2);

    prep1<<<175, 256>>>((const float*)d_in[1], (const float*)d_in[2], (const float*)d_in[3], (const float*)d_in[4],
                        (const float*)d_in[5], (const float*)d_in[6], (const float*)d_in[7], (const float*)d_in[8]);
    prep2<<<111, 256>>>((const float*)d_in[9], (const float*)d_in[10], (const float*)d_in[11], (const float*)d_in[12],
                        (const float*)d_in[13], (const float*)d_in[14], (const float*)d_in[15], (const float*)d_in[16]);

    lstm1<<<dim3(64, 2), 560, smem1>>>(x);
    lstm2<<<dim3(64, 2), 352, smem2>>>();

    dense_head<<<dim3(64, 84), 128>>>((const float*)d_in[17], (const float*)d_in[18],
                                      (const float*)d_in[19], (const float*)d_in[20],
                                      (const float*)d_in[21], (const float*)d_in[22],
                                      (float*)d_out);
}